// round 10
// baseline (speedup 1.0000x reference)
#include <cuda_runtime.h>
#include <cuda_bf16.h>
#include <cstdint>

// SIR SDE: 8192 trajectories x 4900 effective steps, sampled every 100 steps (49 samples),
// features: max, (argmax+u)/49, std(diff(log x)).
//
// R10 = R8 (139.3us best: 128 blocks x 64 thr, per-warp cp.async 3-buffer pipeline,
// burst LDS copy, tail drain, q = rec*s, z = i/DT) + ONE delta: the abs is moved INSIDE
// the sqrt asm block (abs.f32 adjacent to sqrt.approx.f32) so ptxas can fold it into the
// MUFU input modifier (MUFU.SQRT Rd, |Rs|), deleting the 4-cyc FABS link from the serial
// r0 chain (FFMA -> FABS -> MUFU). R6/R8/R9 established the kernel is pinned on exactly
// this chain; instruction count and issue order around it are irrelevant.

#define BSZ    8192
#define CH     20            // steps per chunk; 100 % CH == 0
#define NCHUNK 245           // 4900 effective steps
#define WPB    2             // warps per block
#define THREADS (WPB * 32)

__device__ __forceinline__ void cp_async16(uint32_t saddr, const void* gptr) {
    asm volatile("cp.async.ca.shared.global [%0], [%1], 16;" :: "r"(saddr), "l"(gptr));
}
__device__ __forceinline__ void cp_commit() {
    asm volatile("cp.async.commit_group;");
}
template <int N>
__device__ __forceinline__ void cp_wait() {
    asm volatile("cp.async.wait_group %0;" :: "n"(N));
}
// sqrt(|x|) with the abs adjacent to the sqrt in PTX so ptxas folds it into the MUFU
// input modifier instead of leaving a separate FABS on the dependency chain.
__device__ __forceinline__ float sqrt_abs_approx(float x) {
    float r;
    asm("{ .reg .f32 ta; abs.f32 ta, %1; sqrt.approx.f32 %0, ta; }"
        : "=f"(r) : "f"(x));
    return r;
}

__global__ __launch_bounds__(THREADS, 1)
void sir_sde_kernel(const float* __restrict__ cond,
                    const float* __restrict__ dW,
                    const float* __restrict__ u,
                    float* __restrict__ out)
{
    __shared__ float sdw[WPB][3 * CH * 32];   // per-warp: 3 bufs x 20 steps x 32 lanes

    const int lane = threadIdx.x & 31;
    const int w    = threadIdx.x >> 5;
    const int b0   = blockIdx.x * THREADS + w * 32;   // first trajectory of this warp
    const int b    = b0 + lane;

    // ---------- per-trajectory parameters ----------
    const float inf_rate = cond[b * 4 + 0];
    const float rec      = cond[b * 4 + 1];
    const float mr       = cond[b * 4 + 2];
    const float vol      = cond[b * 4 + 3];

    const float DT      = 0.01f;
    const float r0_init = __fdiv_rn(inf_rate, rec);
    const float sdt     = sqrtf(DT);
    const float dtmr    = DT * mr;
    const float om      = 1.0f - dtmr;        // r0' = om*r0 + c1 + sqrt(|r0|)*c2
    const float c1      = dtmr * r0_init;
    const float kvol    = vol * sdt;
    const float ndtrec  = -DT * rec;          // q' = q + ndtrec*ni
    const float omr     = 1.0f + ndtrec;      // z' = omr*z + ni   (z = i/DT)

    // ---------- state (s -> q = rec*s, i -> z = i/DT) ----------
    float q  = rec * 0.99f;
    float z  = 1.0f;                          // i0 = 0.01 = DT*1
    float r0 = r0_init;

    // ---------- feature accumulators ----------
    float cur_max = -3.402823466e38f;
    int   cur_arg = 0;
    float prev_lg = 0.0f;
    float sumd = 0.0f, sumd2 = 0.0f;

    // ---------- cp.async chunk copier (per warp, self-contained) ----------
    uint32_t smem_base;
    asm("{ .reg .u64 t; cvta.to.shared.u64 t, %1; cvt.u32.u64 %0, t; }"
        : "=r"(smem_base) : "l"(&sdw[w][0]));

    const char* gbase = (const char*)(dW + b0);

    auto issue_chunk = [&](int c, int bufidx) {
        const char* g = gbase + (size_t)c * CH * BSZ * 4;
        uint32_t sb = smem_base + bufidx * (CH * 128);
#pragma unroll
        for (int i = 0; i < 5; ++i) {
            int f   = i * 512 + lane * 16;      // flat byte offset in this warp's buffer
            int row = f >> 7;                   // /128
            int col = f & 127;
            cp_async16(sb + f, g + (size_t)row * BSZ * 4 + col);
        }
        cp_commit();
    };

    // prologue: chunks 0,1 in flight
    issue_chunk(0, 0);
    issue_chunk(1, 1);

    const float* sbuf = &sdw[w][0];

#pragma unroll 1
    for (int c = 0; c < NCHUNK; ++c) {
        // Tail: fewer than 2 groups pending -> wait<1> would not cover chunk c. Full drain.
        if (c >= NCHUNK - 2) cp_wait<0>();
        else                 cp_wait<1>();
        __syncwarp();

        // burst-copy chunk c to registers (conflict-free LDS)
        float dwv[CH];
        const float* sp = sbuf + (c % 3) * (CH * 32) + lane;
#pragma unroll
        for (int k = 0; k < CH; ++k) dwv[k] = sp[k * 32];

        // refill chunk c+2 into buffer (c+2)%3 (last consumer finished a chunk ago)
        if (c + 2 < NCHUNK) issue_chunk(c + 2, (c + 2) % 3);

        // ---------- 20 Euler-Maruyama steps ----------
#pragma unroll
        for (int k = 0; k < CH; ++k) {
            const float c2 = dwv[k] * kvol;     // off the critical chain
            const float ni = r0 * q;            // newly_infected (= r0*rec*s)
            const float sq = sqrt_abs_approx(r0);  // chain: MUFU (abs folded)
            const float t  = fmaf(r0, om, c1);
            r0 = fmaf(sq, c2, t);               // chain: + FFMA
            q  = fmaf(ni, ndtrec, q);
            z  = fmaf(omr, z, ni);              // i-update in one FFMA (z = i/DT)
        }

        // ---------- sample after steps 99, 199, ..., 4899 ----------
        if (c % 5 == 4) {
            const int j = c / 5;
            float x = DT * z;                   // i = DT*z
            if ((__float_as_uint(x) & 0x7f800000u) == 0x7f800000u) x = 0.0f; // nan/inf -> 0
            x = fmaxf(x, 1e-5f);

            if (x > cur_max) { cur_max = x; cur_arg = j; }
            const float lg = logf(x);
            if (j > 0) {
                const float d = lg - prev_lg;
                sumd  += d;
                sumd2 += d * d;
            }
            prev_lg = lg;
        }
    }

    // ---------- features ----------
    const float max_at = ((float)cur_arg + u[b]) / 49.0f;
    const float mean   = sumd * (1.0f / 48.0f);
    float var = sumd2 * (1.0f / 48.0f) - mean * mean;   // ddof=0
    var = fmaxf(var, 0.0f);

    out[b * 3 + 0] = cur_max;
    out[b * 3 + 1] = max_at;
    out[b * 3 + 2] = sqrtf(var);
}

extern "C" void kernel_launch(void* const* d_in, const int* in_sizes, int n_in,
                              void* d_out, int out_size)
{
    const float* cond = (const float*)d_in[0];   // (8192, 4)
    const float* dW   = (const float*)d_in[1];   // (5000, 8192)
    const float* u    = (const float*)d_in[2];   // (8192,)
    float* out        = (float*)d_out;           // (8192, 3)

    sir_sde_kernel<<<BSZ / THREADS, THREADS>>>(cond, dW, u, out);
}

// round 11
// speedup vs baseline: 1.5969x; 1.5969x over previous
#include <cuda_runtime.h>
#include <cuda_bf16.h>
#include <cstdint>

// SIR SDE: 8192 trajectories x 4900 effective steps, sampled every 100 steps (49 samples),
// features: max, (argmax+u)/49, std(diff(log x)).
//
// R11 = R8 (139.3us best) + ONE delta: cp.async pipeline deepened from 3 buffers /
// 2-ahead to 5 buffers / 4-ahead. Cross-round evidence shows dur ~= 160MB / achieved-BW
// in EVERY round -> the kernel is memory-pipeline-bound, and the old pipeline's ~5KB/warp
// in flight was exactly marginal against ~600ns DRAM latency (chunk compute ~= 1 latency).
// Doubling in-flight bytes (~10KB/warp, ~2.6MB chip-wide) should lift achieved BW toward
// 2-3 TB/s until the r0 FP chain (~75-100us equivalent) binds.

#define BSZ    8192
#define CH     20            // steps per chunk; 100 % CH == 0
#define NCHUNK 245           // 4900 effective steps
#define NBUF   5             // smem buffers per warp
#define AHEAD  4             // chunks in flight
#define WPB    2             // warps per block
#define THREADS (WPB * 32)

__device__ __forceinline__ void cp_async16(uint32_t saddr, const void* gptr) {
    asm volatile("cp.async.ca.shared.global [%0], [%1], 16;" :: "r"(saddr), "l"(gptr));
}
__device__ __forceinline__ void cp_commit() {
    asm volatile("cp.async.commit_group;");
}
template <int N>
__device__ __forceinline__ void cp_wait() {
    asm volatile("cp.async.wait_group %0;" :: "n"(N));
}
__device__ __forceinline__ float sqrt_approx(float x) {
    float r;
    asm("sqrt.approx.f32 %0, %1;" : "=f"(r) : "f"(x));
    return r;
}

__global__ __launch_bounds__(THREADS, 1)
void sir_sde_kernel(const float* __restrict__ cond,
                    const float* __restrict__ dW,
                    const float* __restrict__ u,
                    float* __restrict__ out)
{
    __shared__ float sdw[WPB][NBUF * CH * 32];   // per-warp: 5 bufs x 20 steps x 32 lanes

    const int lane = threadIdx.x & 31;
    const int w    = threadIdx.x >> 5;
    const int b0   = blockIdx.x * THREADS + w * 32;   // first trajectory of this warp
    const int b    = b0 + lane;

    // ---------- per-trajectory parameters ----------
    const float inf_rate = cond[b * 4 + 0];
    const float rec      = cond[b * 4 + 1];
    const float mr       = cond[b * 4 + 2];
    const float vol      = cond[b * 4 + 3];

    const float DT      = 0.01f;
    const float r0_init = __fdiv_rn(inf_rate, rec);
    const float sdt     = sqrtf(DT);
    const float dtmr    = DT * mr;
    const float om      = 1.0f - dtmr;        // r0' = om*r0 + c1 + sqrt(|r0|)*c2
    const float c1      = dtmr * r0_init;
    const float kvol    = vol * sdt;
    const float ndtrec  = -DT * rec;          // q' = q + ndtrec*ni
    const float omr     = 1.0f + ndtrec;      // z' = omr*z + ni   (z = i/DT)

    // ---------- state (s -> q = rec*s, i -> z = i/DT) ----------
    float q  = rec * 0.99f;
    float z  = 1.0f;                          // i0 = 0.01 = DT*1
    float r0 = r0_init;

    // ---------- feature accumulators ----------
    float cur_max = -3.402823466e38f;
    int   cur_arg = 0;
    float prev_lg = 0.0f;
    float sumd = 0.0f, sumd2 = 0.0f;

    // ---------- cp.async chunk copier (per warp, self-contained) ----------
    uint32_t smem_base;
    asm("{ .reg .u64 t; cvta.to.shared.u64 t, %1; cvt.u32.u64 %0, t; }"
        : "=r"(smem_base) : "l"(&sdw[w][0]));

    const char* gbase = (const char*)(dW + b0);

    auto issue_chunk = [&](int c, int bufidx) {
        const char* g = gbase + (size_t)c * CH * BSZ * 4;
        uint32_t sb = smem_base + bufidx * (CH * 128);
#pragma unroll
        for (int i = 0; i < 5; ++i) {
            int f   = i * 512 + lane * 16;      // flat byte offset in this warp's buffer
            int row = f >> 7;                   // /128
            int col = f & 127;
            cp_async16(sb + f, g + (size_t)row * BSZ * 4 + col);
        }
        cp_commit();
    };

    // prologue: chunks 0..3 in flight
    issue_chunk(0, 0);
    issue_chunk(1, 1);
    issue_chunk(2, 2);
    issue_chunk(3, 3);

    const float* sbuf = &sdw[w][0];

#pragma unroll 1
    for (int c = 0; c < NCHUNK; ++c) {
        // Steady state: pending groups at this point are {c..c+3} -> wait<3> drains chunk c.
        // Tail (no chunk c+4 issued anymore): pending count shrinks below 4, so wait<3>
        // would no longer cover chunk c -> full drain for the last AHEAD iterations.
        if (c + AHEAD >= NCHUNK) cp_wait<0>();
        else                     cp_wait<3>();
        __syncwarp();

        // burst-copy chunk c to registers (conflict-free LDS)
        float dwv[CH];
        const float* sp = sbuf + (c % NBUF) * (CH * 32) + lane;
#pragma unroll
        for (int k = 0; k < CH; ++k) dwv[k] = sp[k * 32];

        // refill chunk c+AHEAD into buffer (c+AHEAD)%NBUF (its last consumer is long done)
        if (c + AHEAD < NCHUNK) issue_chunk(c + AHEAD, (c + AHEAD) % NBUF);

        // ---------- 20 Euler-Maruyama steps ----------
#pragma unroll
        for (int k = 0; k < CH; ++k) {
            const float c2 = dwv[k] * kvol;     // off the critical chain
            const float ni = r0 * q;            // newly_infected (= r0*rec*s)
            const float sq = sqrt_approx(fabsf(r0));
            const float t  = fmaf(r0, om, c1);
            r0 = fmaf(sq, c2, t);               // chain: MUFU + FFMA
            q  = fmaf(ni, ndtrec, q);
            z  = fmaf(omr, z, ni);              // i-update in one FFMA (z = i/DT)
        }

        // ---------- sample after steps 99, 199, ..., 4899 ----------
        if (c % 5 == 4) {
            const int j = c / 5;
            float x = DT * z;                   // i = DT*z
            if ((__float_as_uint(x) & 0x7f800000u) == 0x7f800000u) x = 0.0f; // nan/inf -> 0
            x = fmaxf(x, 1e-5f);

            if (x > cur_max) { cur_max = x; cur_arg = j; }
            const float lg = logf(x);
            if (j > 0) {
                const float d = lg - prev_lg;
                sumd  += d;
                sumd2 += d * d;
            }
            prev_lg = lg;
        }
    }

    // ---------- features ----------
    const float max_at = ((float)cur_arg + u[b]) / 49.0f;
    const float mean   = sumd * (1.0f / 48.0f);
    float var = sumd2 * (1.0f / 48.0f) - mean * mean;   // ddof=0
    var = fmaxf(var, 0.0f);

    out[b * 3 + 0] = cur_max;
    out[b * 3 + 1] = max_at;
    out[b * 3 + 2] = sqrtf(var);
}

extern "C" void kernel_launch(void* const* d_in, const int* in_sizes, int n_in,
                              void* d_out, int out_size)
{
    const float* cond = (const float*)d_in[0];   // (8192, 4)
    const float* dW   = (const float*)d_in[1];   // (5000, 8192)
    const float* u    = (const float*)d_in[2];   // (8192,)
    float* out        = (float*)d_out;           // (8192, 3)

    sir_sde_kernel<<<BSZ / THREADS, THREADS>>>(cond, dW, u, out);
}